// round 12
// baseline (speedup 1.0000x reference)
#include <cuda_runtime.h>
#include <cuda_bf16.h>

#define B_   4
#define C_   64
#define O_   64
#define H_   128
#define W_   128
#define KK   9
#define HW_  (H_ * W_)

// ---------------- device scratch (allocation-free rule) ----------------
__device__ float4 g_x4[B_ * C_ * HW_];   // (x[y][x], x[y][x+1], x[y+1][x], x[y+1][x+1])
__device__ uint2  g_wB[KK * 2 * 8 * 8 * 32];  // [k][plane][kt][nt][lane] -> (b0,b1)

// ---------------- prep kernels ----------------
__global__ void prep_w(const float* __restrict__ w) {
    int i = blockIdx.x * 256 + threadIdx.x;          // over O*C*KK = 36864
    if (i < O_ * C_ * KK) {
        int o = i / (C_ * KK);
        int r = i - o * (C_ * KK);
        int c = r / KK;
        int k = r - c * KK;
        float v = w[i];
        unsigned hb = __float_as_uint(v) & 0xFFFF0000u;       // bf16 truncation
        float lf = v - __uint_as_float(hb);
        unsigned h16 = hb >> 16;
        unsigned l16 = (unsigned)__bfloat16_as_ushort(__float2bfloat16(lf));
        unsigned hword = h16 | (h16 << 16);                    // (wh, wh) k-pair
        unsigned lword = l16 | (l16 << 16);                    // (wl, wl) k-pair
        int kt = c >> 3, cl = c & 7;
        int j  = cl >> 2, tg = cl & 3;
        int nt = o >> 3;
        int lane = ((o & 7) << 2) | tg;
        unsigned* bh = (unsigned*)&g_wB[(((k * 2 + 0) * 8 + kt) * 8 + nt) * 32 + lane];
        unsigned* bl = (unsigned*)&g_wB[(((k * 2 + 1) * 8 + kt) * 8 + nt) * 32 + lane];
        bh[j] = hword;
        bl[j] = lword;
    }
}

__global__ void prep_x4(const float* __restrict__ x) {
    int i = blockIdx.x * 256 + threadIdx.x;          // over B*C*HW
    if (i < B_ * C_ * HW_) {
        int col = i & (W_ - 1);
        int y   = (i >> 7) & (H_ - 1);
        float a = x[i];
        float b = (col < W_ - 1) ? x[i + 1] : a;
        float c, d;
        if (y < H_ - 1) {
            c = x[i + W_];
            d = (col < W_ - 1) ? x[i + W_ + 1] : c;
        } else { c = a; d = b; }
        g_x4[i] = make_float4(a, b, c, d);
    }
}

// ---------------- main kernel ----------------
// 512 blocks (batch*row), 512 threads, 1 CTA/SM.
// Every warp: samples (px, 16-channel quarter) AND runs MMA (32px x 16o tile).
// Software pipeline per tap: issue gathers(k+1) -> MMA(k) -> cvt+STS(k+1) -> sync.
// smem: A tiles double-buffered [2][128 px][128 k' bf16] = 2 * 32KB
//       row = 256B = 16 units of 16B; unit u stored at u ^ (px & 7)  (XOR swizzle)
#define A_BUF_BYTES 32768
#define SMEM_TOTAL  (2 * A_BUF_BYTES)

#define LDMX4(r0, r1, r2, r3, addr)                                          \
    asm volatile("ldmatrix.sync.aligned.m8n8.x4.shared.b16 {%0,%1,%2,%3}, [%4];" \
        : "=r"(r0), "=r"(r1), "=r"(r2), "=r"(r3) : "r"(addr))

#define MMA_BF16(d, a0, a1, a2, a3, b0, b1)                                  \
    asm volatile("mma.sync.aligned.m16n8k16.row.col.f32.bf16.bf16.f32 "      \
        "{%0,%1,%2,%3}, {%4,%5,%6,%7}, {%8,%9}, {%0,%1,%2,%3};"              \
        : "+f"((d)[0]), "+f"((d)[1]), "+f"((d)[2]), "+f"((d)[3])             \
        : "r"(a0), "r"(a1), "r"(a2), "r"(a3), "r"(b0), "r"(b1))

__global__ __launch_bounds__(512, 1)
void dconv_main(const float* __restrict__ offset,
                const float* __restrict__ bias,
                float* __restrict__ out) {
    extern __shared__ char smc[];
    unsigned smb;
    asm("{ .reg .u64 t; cvta.to.shared.u64 t, %1; cvt.u32.u64 %0, t; }"
        : "=r"(smb) : "l"(smc));

    const int tid   = threadIdx.x;
    const int batch = blockIdx.x >> 7;
    const int ho    = blockIdx.x & 127;

    // ---- sampling identity: thread = (px, channel quarter) ----
    const int px = tid & 127;
    const int cq = tid >> 7;                 // 0..3 -> channels cq*16 .. cq*16+15
    const float4* xb4  = g_x4 + (batch * C_ + cq * 16) * HW_;
    const float*  offb = offset + (batch * 2 * KK) * HW_ + ho * W_ + px;
    const unsigned ArowBase = smb + (unsigned)(px * 256);
    const unsigned sw3      = (unsigned)(px & 7);

    // ---- MMA identity: warp = (pxb: 32-px block, og: 16-o group) ----
    const int wc   = tid >> 5;               // 0..15
    const int pxb  = wc & 3;
    const int og   = wc >> 2;                // 0..3
    const int lane = tid & 31;
    const int pxl  = lane & 15;
    const int usel = lane >> 4;

    float4 t[16];
    float  u0, u1, u2, u3;

    // gather for tap k: bilinear folds + 16 front-issued LDG.128
    auto gather = [&](int k) {
        const float offy = __ldg(offb + (2 * k) * HW_);
        const float offx = __ldg(offb + (2 * k + 1) * HW_);
        const int ki = k / 3, kj = k - ki * 3;
        const float py  = offy + (float)(ki - 1 + ho);
        const float pxx = offx + (float)(kj - 1 + px);
        const float y0f = floorf(py), x0f = floorf(pxx);
        const float ly = py - y0f,  lx = pxx - x0f;
        const float hy = 1.f - ly,  hx = 1.f - lx;
        const int y0 = (int)y0f, x0 = (int)x0f;

        int ybase; float w_top, w_bot;
        if (y0 >= 0) {
            ybase = min(y0, H_ - 1);
            w_top = (y0 < H_)     ? hy : 0.f;
            w_bot = (y0 < H_ - 1) ? ly : 0.f;
        } else {
            ybase = 0;
            w_top = (y0 == -1) ? ly : 0.f;
            w_bot = 0.f;
        }
        float wa, wb;
        if (x0 >= 0 && x0 < W_) { wa = hx; wb = (x0 < W_ - 1) ? lx : 0.f; }
        else if (x0 == -1)      { wa = lx; wb = 0.f; }
        else                    { wa = 0.f; wb = 0.f; }
        const int bx = min(max(x0, 0), W_ - 1);

        u0 = w_top * wa; u1 = w_top * wb;
        u2 = w_bot * wa; u3 = w_bot * wb;

        const float4* q = xb4 + ybase * W_ + bx;
        #pragma unroll
        for (int cc = 0; cc < 16; cc++)
            t[cc] = __ldg(q + cc * HW_);     // MLP=16 front-issued gathers
    };

    // convert + store into buffer s
    auto cvtsts = [&](int s) {
        const unsigned Arow = ArowBase + (unsigned)s * A_BUF_BYTES;
        #pragma unroll
        for (int j = 0; j < 4; j++) {
            unsigned wbuf[4];
            #pragma unroll
            for (int cc = 0; cc < 4; cc++) {
                const float4 tt = t[j * 4 + cc];
                const float v = u0 * tt.x + u1 * tt.y + u2 * tt.z + u3 * tt.w;
                const unsigned hb = __float_as_uint(v) & 0xFFFF0000u;
                const float lf = v - __uint_as_float(hb);
                const unsigned l16 =
                    (unsigned)__bfloat16_as_ushort(__float2bfloat16(lf));
                wbuf[cc] = (hb >> 16) | (l16 << 16);   // (vh, vl) k'-pair
            }
            const unsigned u = (unsigned)(cq * 4 + j);
            const unsigned addr = Arow + ((u ^ sw3) << 4);
            asm volatile("st.shared.v4.b32 [%0], {%1,%2,%3,%4};"
                :: "r"(addr), "r"(wbuf[0]), "r"(wbuf[1]),
                   "r"(wbuf[2]), "r"(wbuf[3]));
        }
    };

    float acc[2][2][4];                      // [mt][ntl][quad]
    #pragma unroll
    for (int mt = 0; mt < 2; mt++)
        #pragma unroll
        for (int nt = 0; nt < 2; nt++)
            #pragma unroll
            for (int q = 0; q < 4; q++) acc[mt][nt][q] = 0.f;

    // ---------------- prologue: sample tap 0 ----------------
    gather(0);
    cvtsts(0);
    __syncthreads();

    // ---------------- pipelined main loop ----------------
    for (int k = 0; k < KK; k++) {
        const int s = k & 1;

        if (k < KK - 1) gather(k + 1);       // LDGs in flight during MMA below

        // ---- MMA phase for tap k ----
        {
            const unsigned Abase = smb + (unsigned)s * A_BUF_BYTES;
            const uint2* wB = g_wB + k * 4096 + (og * 2) * 32 + lane;

            #pragma unroll
            for (int kt = 0; kt < 8; kt++) {
                uint2 bh[2], bl[2];
                #pragma unroll
                for (int ntl = 0; ntl < 2; ntl++) {
                    bh[ntl] = __ldg(wB + (0 * 64 + kt * 8 + ntl) * 32);
                    bl[ntl] = __ldg(wB + (1 * 64 + kt * 8 + ntl) * 32);
                }
                unsigned a[2][4];
                #pragma unroll
                for (int mt = 0; mt < 2; mt++) {
                    const int px_l = pxb * 32 + mt * 16 + pxl;
                    const unsigned uu = (unsigned)(2 * kt + usel);
                    const unsigned addr = Abase + (unsigned)(px_l * 256)
                                        + ((uu ^ (unsigned)(px_l & 7)) << 4);
                    LDMX4(a[mt][0], a[mt][1], a[mt][2], a[mt][3], addr);
                }
                #pragma unroll
                for (int ntl = 0; ntl < 2; ntl++) {
                    MMA_BF16(acc[0][ntl], a[0][0], a[0][1], a[0][2], a[0][3],
                             bh[ntl].x, bh[ntl].y);
                    MMA_BF16(acc[1][ntl], a[1][0], a[1][1], a[1][2], a[1][3],
                             bh[ntl].x, bh[ntl].y);
                }
                #pragma unroll
                for (int ntl = 0; ntl < 2; ntl++) {
                    MMA_BF16(acc[0][ntl], a[0][0], a[0][1], a[0][2], a[0][3],
                             bl[ntl].x, bl[ntl].y);
                    MMA_BF16(acc[1][ntl], a[1][0], a[1][1], a[1][2], a[1][3],
                             bl[ntl].x, bl[ntl].y);
                }
            }
        }

        if (k < KK - 1) {
            cvtsts(s ^ 1);                   // write tap k+1 into other buffer
            __syncthreads();
        }
    }

    // ---------------- epilogue ----------------
    const int g = lane >> 2, tg = lane & 3;
    #pragma unroll
    for (int ntl = 0; ntl < 2; ntl++) {
        const int o = og * 16 + ntl * 8 + 2 * tg;
        const float b0 = __ldg(bias + o);
        const float b1 = __ldg(bias + o + 1);
        float* o0 = out + (batch * O_ + o) * HW_ + ho * W_;
        float* o1 = o0 + HW_;
        #pragma unroll
        for (int mt = 0; mt < 2; mt++) {
            const int wo = pxb * 32 + mt * 16 + g;
            o0[wo]     = acc[mt][ntl][0] + b0;
            o1[wo]     = acc[mt][ntl][1] + b1;
            o0[wo + 8] = acc[mt][ntl][2] + b0;
            o1[wo + 8] = acc[mt][ntl][3] + b1;
        }
    }
}

extern "C" void kernel_launch(void* const* d_in, const int* in_sizes, int n_in,
                              void* d_out, int out_size) {
    const float* x      = (const float*)d_in[0];
    const float* offset = (const float*)d_in[1];
    const float* weight = (const float*)d_in[2];
    const float* bias   = (const float*)d_in[3];
    float* out = (float*)d_out;

    cudaFuncSetAttribute(dconv_main,
                         cudaFuncAttributeMaxDynamicSharedMemorySize, SMEM_TOTAL);

    prep_w<<<(O_ * C_ * KK + 255) / 256, 256>>>(weight);
    prep_x4<<<(B_ * C_ * HW_ + 255) / 256, 256>>>(x);
    dconv_main<<<B_ * H_, 512, SMEM_TOTAL>>>(offset, bias, out);
}

// round 13
// speedup vs baseline: 1.4451x; 1.4451x over previous
#include <cuda_runtime.h>
#include <cuda_bf16.h>

#define B_   4
#define C_   64
#define O_   64
#define H_   128
#define W_   128
#define KK   9
#define HW_  (H_ * W_)

// ---------------- device scratch (allocation-free rule) ----------------
__device__ float4 g_x4[B_ * C_ * HW_];   // (x[y][x], x[y][x+1], x[y+1][x], x[y+1][x+1])
// B fragments, full-K: [k][plane(h/l)][kt(4)][nt(8)][lane(32)] uint2
__device__ uint2  g_wB[KK * 2 * 4 * 8 * 32];

#define NWBLK 144
#define NXBLK 16384

// ---------------- merged prep kernel (2 launches/replay -> ncu hits main) ----
__global__ void prep_all(const float* __restrict__ w, const float* __restrict__ x) {
    if (blockIdx.x < NWBLK) {
        int i = blockIdx.x * 256 + threadIdx.x;      // over O*C*KK = 36864
        if (i < O_ * C_ * KK) {
            int o = i / (C_ * KK);
            int r = i - o * (C_ * KK);
            int c = r / KK;
            int k = r - c * KK;
            float v = w[i];
            unsigned hb = __float_as_uint(v) & 0xFFFF0000u;   // bf16 trunc hi
            float lf = v - __uint_as_float(hb);
            unsigned short h16 = (unsigned short)(hb >> 16);
            unsigned short l16 = __bfloat16_as_ushort(__float2bfloat16(lf));
            // k-slot within kt block = real channel index s (0..15)
            int kt = c >> 4, s = c & 15;
            int halfsel = s >> 3;          // selects uint2 .x / .y
            int tg = (s & 7) >> 1;         // lane thread-group
            int hilo = s & 1;              // low/high bf16 in word
            int nt = o >> 3, lane = ((o & 7) << 2) | tg;
            unsigned short* p = (unsigned short*)g_wB;
            // ushort index: [(k*2+plane)*4+kt][nt][lane] uint2 = 4 ushorts
            int base = (((k * 2 + 0) * 4 + kt) * 8 * 32 + nt * 32 + lane) * 4
                     + halfsel * 2 + hilo;
            int plane_off = 4 * 8 * 32 * 4;           // 4096 ushorts
            p[base]             = h16;                // plane h
            p[base + plane_off] = l16;                // plane l
        }
    } else {
        int i = (blockIdx.x - NWBLK) * 256 + threadIdx.x;   // over B*C*HW
        int col = i & (W_ - 1);
        int y   = (i >> 7) & (H_ - 1);
        float a = x[i];
        float b = (col < W_ - 1) ? x[i + 1] : a;
        float c, d;
        if (y < H_ - 1) {
            c = x[i + W_];
            d = (col < W_ - 1) ? x[i + W_ + 1] : c;
        } else { c = a; d = b; }
        g_x4[i] = make_float4(a, b, c, d);
    }
}

// ---------------- main kernel ----------------
// 512 blocks (batch*row), 512 threads, 1 CTA/SM:
//   warps 0-7 producers (128px x 2 chalf); warps 8-15 consumers (32px x 32o)
// smem per stage (32KB): A_h [128px][64ch bf16] (16KB) then A_l (16KB).
//   row = 128B = 8 units of 16B; unit u stored at u ^ (px & 7)  (XOR swizzle)
#define A_BUF_BYTES 32768
#define A_PLANE     16384
#define SMEM_TOTAL  (2 * A_BUF_BYTES)

#define BSYNC(id)   asm volatile("bar.sync %0, 512;"   :: "r"(id) : "memory")
#define BARRIVE(id) asm volatile("bar.arrive %0, 512;" :: "r"(id) : "memory")

#define LDMX4(r, addr)                                                       \
    asm volatile("ldmatrix.sync.aligned.m8n8.x4.shared.b16 {%0,%1,%2,%3}, [%4];" \
        : "=r"((r)[0]), "=r"((r)[1]), "=r"((r)[2]), "=r"((r)[3]) : "r"(addr))

#define MMA_BF16(d, a, b0, b1)                                               \
    asm volatile("mma.sync.aligned.m16n8k16.row.col.f32.bf16.bf16.f32 "      \
        "{%0,%1,%2,%3}, {%4,%5,%6,%7}, {%8,%9}, {%0,%1,%2,%3};"              \
        : "+f"((d)[0]), "+f"((d)[1]), "+f"((d)[2]), "+f"((d)[3])             \
        : "r"((a)[0]), "r"((a)[1]), "r"((a)[2]), "r"((a)[3]), "r"(b0), "r"(b1))

__global__ __launch_bounds__(512, 1)
void dconv_main(const float* __restrict__ offset,
                const float* __restrict__ bias,
                float* __restrict__ out) {
    extern __shared__ char smc[];
    unsigned smb;
    asm("{ .reg .u64 t; cvta.to.shared.u64 t, %1; cvt.u32.u64 %0, t; }"
        : "=r"(smb) : "l"(smc));

    const int tid   = threadIdx.x;
    const int batch = blockIdx.x >> 7;
    const int ho    = blockIdx.x & 127;

    if (tid < 256) {
        // ================= PRODUCERS (warps 0-7) =================
        const int px    = tid & 127;
        const int chalf = tid >> 7;          // 32 channels each
        const float4* xb4  = g_x4 + (batch * C_ + chalf * 32) * HW_;
        const float*  offb = offset + (batch * 2 * KK) * HW_ + ho * W_ + px;

        float offy[KK], offx[KK];
        #pragma unroll
        for (int k = 0; k < KK; k++) {
            offy[k] = __ldg(offb + (2 * k) * HW_);
            offx[k] = __ldg(offb + (2 * k + 1) * HW_);
        }

        for (int k = 0; k < KK; k++) {
            const int s = k & 1;
            if (k >= 2) BSYNC(3 + s);        // wait stage empty

            // bilinear corner math (proven)
            const int ki = k / 3, kj = k - ki * 3;
            const float py  = offy[k] + (float)(ki - 1 + ho);
            const float pxx = offx[k] + (float)(kj - 1 + px);
            const float y0f = floorf(py), x0f = floorf(pxx);
            const float ly = py - y0f,  lx = pxx - x0f;
            const float hy = 1.f - ly,  hx = 1.f - lx;
            const int y0 = (int)y0f, x0 = (int)x0f;

            int ybase; float w_top, w_bot;
            if (y0 >= 0) {
                ybase = min(y0, H_ - 1);
                w_top = (y0 < H_)     ? hy : 0.f;
                w_bot = (y0 < H_ - 1) ? ly : 0.f;
            } else {
                ybase = 0;
                w_top = (y0 == -1) ? ly : 0.f;
                w_bot = 0.f;
            }
            float wa, wb;
            if (x0 >= 0 && x0 < W_) { wa = hx; wb = (x0 < W_ - 1) ? lx : 0.f; }
            else if (x0 == -1)      { wa = lx; wb = 0.f; }
            else                    { wa = 0.f; wb = 0.f; }
            const int bx = min(max(x0, 0), W_ - 1);

            const float u0 = w_top * wa, u1 = w_top * wb;
            const float u2 = w_bot * wa, u3 = w_bot * wb;

            const float4* q = xb4 + ybase * W_ + bx;
            const unsigned Ah = smb + (unsigned)s * A_BUF_BYTES + (unsigned)(px * 128);
            const unsigned Al = Ah + A_PLANE;
            const unsigned sw3 = (unsigned)(px & 7);

            // 2 batches of 16 front-issued gathers (MLP=16)
            #pragma unroll
            for (int half = 0; half < 2; half++) {
                float4 t[16];
                #pragma unroll
                for (int cc = 0; cc < 16; cc++)
                    t[cc] = __ldg(q + (half * 16 + cc) * HW_);

                unsigned hw[8], lw[8];
                #pragma unroll
                for (int i = 0; i < 8; i++) {
                    const float4 ta = t[2 * i], tb = t[2 * i + 1];
                    const float v0 = u0 * ta.x + u1 * ta.y + u2 * ta.z + u3 * ta.w;
                    const float v1 = u0 * tb.x + u1 * tb.y + u2 * tb.z + u3 * tb.w;
                    const unsigned h0 = __float_as_uint(v0) & 0xFFFF0000u;
                    const unsigned h1 = __float_as_uint(v1) & 0xFFFF0000u;
                    const unsigned l0 = (unsigned)__bfloat16_as_ushort(
                        __float2bfloat16(v0 - __uint_as_float(h0)));
                    const unsigned l1 = (unsigned)__bfloat16_as_ushort(
                        __float2bfloat16(v1 - __uint_as_float(h1)));
                    hw[i] = (h0 >> 16) | h1;           // (vh_c, vh_c+1)
                    lw[i] = l0 | (l1 << 16);           // (vl_c, vl_c+1)
                }
                #pragma unroll
                for (int j = 0; j < 2; j++) {
                    const unsigned u = (unsigned)(chalf * 4 + half * 2 + j);
                    const unsigned off = ((u ^ sw3) << 4);
                    asm volatile("st.shared.v4.b32 [%0], {%1,%2,%3,%4};"
                        :: "r"(Ah + off), "r"(hw[4 * j]), "r"(hw[4 * j + 1]),
                           "r"(hw[4 * j + 2]), "r"(hw[4 * j + 3]));
                    asm volatile("st.shared.v4.b32 [%0], {%1,%2,%3,%4};"
                        :: "r"(Al + off), "r"(lw[4 * j]), "r"(lw[4 * j + 1]),
                           "r"(lw[4 * j + 2]), "r"(lw[4 * j + 3]));
                }
            }

            BARRIVE(1 + s);                  // stage full
        }
    } else {
        // ================= CONSUMERS (warps 8-15) =================
        const int wc   = (tid >> 5) - 8;     // 0..7
        const int pxb  = wc & 3;
        const int oh   = wc >> 2;
        const int lane = tid & 31;
        const int pxl  = lane & 15;
        const int usel = lane >> 4;

        float acc[2][4][4];                  // [mt][ntl][quad]
        #pragma unroll
        for (int mt = 0; mt < 2; mt++)
            #pragma unroll
            for (int nt = 0; nt < 4; nt++)
                #pragma unroll
                for (int q = 0; q < 4; q++) acc[mt][nt][q] = 0.f;

        for (int k = 0; k < KK; k++) {
            const int s = k & 1;
            BSYNC(1 + s);                    // wait stage full

            const unsigned AhB = smb + (unsigned)s * A_BUF_BYTES;
            const unsigned AlB = AhB + A_PLANE;
            const uint2* wBh = g_wB + k * 2048 + lane;   // plane h
            const uint2* wBl = wBh + 1024;               // plane l

            #pragma unroll
            for (int kt = 0; kt < 4; kt++) {
                // front-issue B fragments (coalesced uint2 LDG, L1-hot)
                uint2 bh[4], bl[4];
                #pragma unroll
                for (int ntl = 0; ntl < 4; ntl++) {
                    const int o = kt * 256 + (oh * 4 + ntl) * 32;
                    bh[ntl] = __ldg(wBh + o);
                    bl[ntl] = __ldg(wBl + o);
                }

                unsigned ah[2][4], al[2][4];
                #pragma unroll
                for (int mt = 0; mt < 2; mt++) {
                    const int px_l = pxb * 32 + mt * 16 + pxl;
                    const unsigned u = (unsigned)(2 * kt + usel);
                    const unsigned off = (unsigned)(px_l * 128)
                                       + ((u ^ (unsigned)(px_l & 7)) << 4);
                    LDMX4(ah[mt], AhB + off);
                    LDMX4(al[mt], AlB + off);
                }

                // 3 products: Ah*Bh, Al*Bh, Ah*Bl  (ll dropped, ~2^-14)
                #pragma unroll
                for (int ntl = 0; ntl < 4; ntl++) {
                    MMA_BF16(acc[0][ntl], ah[0], bh[ntl].x, bh[ntl].y);
                    MMA_BF16(acc[1][ntl], ah[1], bh[ntl].x, bh[ntl].y);
                }
                #pragma unroll
                for (int ntl = 0; ntl < 4; ntl++) {
                    MMA_BF16(acc[0][ntl], al[0], bh[ntl].x, bh[ntl].y);
                    MMA_BF16(acc[1][ntl], al[1], bh[ntl].x, bh[ntl].y);
                }
                #pragma unroll
                for (int ntl = 0; ntl < 4; ntl++) {
                    MMA_BF16(acc[0][ntl], ah[0], bl[ntl].x, bl[ntl].y);
                    MMA_BF16(acc[1][ntl], ah[1], bl[ntl].x, bl[ntl].y);
                }
            }

            BARRIVE(3 + s);                  // stage empty
        }

        // ---------------- epilogue ----------------
        const int g = lane >> 2, tg = lane & 3;
        #pragma unroll
        for (int ntl = 0; ntl < 4; ntl++) {
            const int o = oh * 32 + ntl * 8 + 2 * tg;
            const float b0 = __ldg(bias + o);
            const float b1 = __ldg(bias + o + 1);
            float* o0 = out + (batch * O_ + o) * HW_ + ho * W_;
            float* o1 = o0 + HW_;
            #pragma unroll
            for (int mt = 0; mt < 2; mt++) {
                const int wo = pxb * 32 + mt * 16 + g;
                o0[wo]     = acc[mt][ntl][0] + b0;
                o1[wo]     = acc[mt][ntl][1] + b1;
                o0[wo + 8] = acc[mt][ntl][2] + b0;
                o1[wo + 8] = acc[mt][ntl][3] + b1;
            }
        }
    }
}

extern "C" void kernel_launch(void* const* d_in, const int* in_sizes, int n_in,
                              void* d_out, int out_size) {
    const float* x      = (const float*)d_in[0];
    const float* offset = (const float*)d_in[1];
    const float* weight = (const float*)d_in[2];
    const float* bias   = (const float*)d_in[3];
    float* out = (float*)d_out;

    cudaFuncSetAttribute(dconv_main,
                         cudaFuncAttributeMaxDynamicSharedMemorySize, SMEM_TOTAL);

    prep_all<<<NWBLK + NXBLK, 256>>>(weight, x);
    dconv_main<<<B_ * H_, 512, SMEM_TOTAL>>>(offset, bias, out);
}

// round 14
// speedup vs baseline: 1.4659x; 1.0144x over previous
#include <cuda_runtime.h>
#include <cuda_bf16.h>

#define B_   4
#define C_   64
#define O_   64
#define H_   128
#define W_   128
#define KK   9
#define HW_  (H_ * W_)

// ---------------- device scratch (allocation-free rule) ----------------
__device__ float4 g_x4[B_ * C_ * HW_];   // (x[y][x], x[y][x+1], x[y+1][x], x[y+1][x+1])
// B fragments, full-K: [k][plane(h/l)][kt(4)][nt(8)][lane(32)] uint2
__device__ uint2  g_wB[KK * 2 * 4 * 8 * 32];

#define NWBLK 144
#define NXBLK 16384

// ---------------- merged prep kernel ----------------
__global__ void prep_all(const float* __restrict__ w, const float* __restrict__ x) {
    if (blockIdx.x < NWBLK) {
        int i = blockIdx.x * 256 + threadIdx.x;      // over O*C*KK = 36864
        if (i < O_ * C_ * KK) {
            int o = i / (C_ * KK);
            int r = i - o * (C_ * KK);
            int c = r / KK;
            int k = r - c * KK;
            float v = w[i];
            unsigned hb = __float_as_uint(v) & 0xFFFF0000u;   // bf16 trunc hi
            float lf = v - __uint_as_float(hb);
            unsigned short h16 = (unsigned short)(hb >> 16);
            unsigned short l16 = __bfloat16_as_ushort(__float2bfloat16(lf));
            int kt = c >> 4, s = c & 15;
            int halfsel = s >> 3;
            int tg = (s & 7) >> 1;
            int hilo = s & 1;
            int nt = o >> 3, lane = ((o & 7) << 2) | tg;
            unsigned short* p = (unsigned short*)g_wB;
            int base = (((k * 2 + 0) * 4 + kt) * 8 * 32 + nt * 32 + lane) * 4
                     + halfsel * 2 + hilo;
            int plane_off = 4 * 8 * 32 * 4;           // 4096 ushorts
            p[base]             = h16;                // plane h
            p[base + plane_off] = l16;                // plane l
        }
    } else {
        int i = (blockIdx.x - NWBLK) * 256 + threadIdx.x;   // over B*C*HW
        int col = i & (W_ - 1);
        int y   = (i >> 7) & (H_ - 1);
        float a = x[i];
        float b = (col < W_ - 1) ? x[i + 1] : a;
        float c, d;
        if (y < H_ - 1) {
            c = x[i + W_];
            d = (col < W_ - 1) ? x[i + W_ + 1] : c;
        } else { c = a; d = b; }
        g_x4[i] = make_float4(a, b, c, d);
    }
}

// ---------------- main kernel ----------------
// 512 blocks (batch*row), 512 threads, 1 CTA/SM:
//   warps 0-7 producers (128px x 2 chalf); warps 8-15 consumers (32px x 32o)
// smem: 4-STAGE ring of A tiles, 4 * 32KB = 128KB.
//   per stage: A_h [128px][64ch bf16] (16KB) then A_l (16KB)
//   row = 128B = 8 units of 16B; unit u stored at u ^ (px & 7)  (XOR swizzle)
#define A_BUF_BYTES 32768
#define A_PLANE     16384
#define NSTAGE      4
#define SMEM_TOTAL  (NSTAGE * A_BUF_BYTES)

// named barriers: 1+s = "stage s full", 5+s = "stage s empty"; 512 total arrivals
#define BSYNC(id)   asm volatile("bar.sync %0, 512;"   :: "r"(id) : "memory")
#define BARRIVE(id) asm volatile("bar.arrive %0, 512;" :: "r"(id) : "memory")

#define LDMX4(r, addr)                                                       \
    asm volatile("ldmatrix.sync.aligned.m8n8.x4.shared.b16 {%0,%1,%2,%3}, [%4];" \
        : "=r"((r)[0]), "=r"((r)[1]), "=r"((r)[2]), "=r"((r)[3]) : "r"(addr))

#define MMA_BF16(d, a, b0, b1)                                               \
    asm volatile("mma.sync.aligned.m16n8k16.row.col.f32.bf16.bf16.f32 "      \
        "{%0,%1,%2,%3}, {%4,%5,%6,%7}, {%8,%9}, {%0,%1,%2,%3};"              \
        : "+f"((d)[0]), "+f"((d)[1]), "+f"((d)[2]), "+f"((d)[3])             \
        : "r"((a)[0]), "r"((a)[1]), "r"((a)[2]), "r"((a)[3]), "r"(b0), "r"(b1))

__global__ __launch_bounds__(512, 1)
void dconv_main(const float* __restrict__ offset,
                const float* __restrict__ bias,
                float* __restrict__ out) {
    extern __shared__ char smc[];
    unsigned smb;
    asm("{ .reg .u64 t; cvta.to.shared.u64 t, %1; cvt.u32.u64 %0, t; }"
        : "=r"(smb) : "l"(smc));

    const int tid   = threadIdx.x;
    const int batch = blockIdx.x >> 7;
    const int ho    = blockIdx.x & 127;

    if (tid < 256) {
        // ================= PRODUCERS (warps 0-7) =================
        const int px    = tid & 127;
        const int chalf = tid >> 7;          // 32 channels each
        const float4* xb4  = g_x4 + (batch * C_ + chalf * 32) * HW_;
        const float*  offb = offset + (batch * 2 * KK) * HW_ + ho * W_ + px;

        float offy[KK], offx[KK];
        #pragma unroll
        for (int k = 0; k < KK; k++) {
            offy[k] = __ldg(offb + (2 * k) * HW_);
            offx[k] = __ldg(offb + (2 * k + 1) * HW_);
        }

        for (int k = 0; k < KK; k++) {
            const int s = k & (NSTAGE - 1);
            if (k >= NSTAGE) BSYNC(5 + s);   // wait stage empty

            // bilinear corner math (proven)
            const int ki = k / 3, kj = k - ki * 3;
            const float py  = offy[k] + (float)(ki - 1 + ho);
            const float pxx = offx[k] + (float)(kj - 1 + px);
            const float y0f = floorf(py), x0f = floorf(pxx);
            const float ly = py - y0f,  lx = pxx - x0f;
            const float hy = 1.f - ly,  hx = 1.f - lx;
            const int y0 = (int)y0f, x0 = (int)x0f;

            int ybase; float w_top, w_bot;
            if (y0 >= 0) {
                ybase = min(y0, H_ - 1);
                w_top = (y0 < H_)     ? hy : 0.f;
                w_bot = (y0 < H_ - 1) ? ly : 0.f;
            } else {
                ybase = 0;
                w_top = (y0 == -1) ? ly : 0.f;
                w_bot = 0.f;
            }
            float wa, wb;
            if (x0 >= 0 && x0 < W_) { wa = hx; wb = (x0 < W_ - 1) ? lx : 0.f; }
            else if (x0 == -1)      { wa = lx; wb = 0.f; }
            else                    { wa = 0.f; wb = 0.f; }
            const int bx = min(max(x0, 0), W_ - 1);

            const float u0 = w_top * wa, u1 = w_top * wb;
            const float u2 = w_bot * wa, u3 = w_bot * wb;

            const float4* q = xb4 + ybase * W_ + bx;
            const unsigned Ah = smb + (unsigned)s * A_BUF_BYTES + (unsigned)(px * 128);
            const unsigned Al = Ah + A_PLANE;
            const unsigned sw3 = (unsigned)(px & 7);

            // 2 batches of 16 front-issued gathers (MLP=16)
            #pragma unroll
            for (int half = 0; half < 2; half++) {
                float4 t[16];
                #pragma unroll
                for (int cc = 0; cc < 16; cc++)
                    t[cc] = __ldg(q + (half * 16 + cc) * HW_);

                unsigned hw[8], lw[8];
                #pragma unroll
                for (int i = 0; i < 8; i++) {
                    const float4 ta = t[2 * i], tb = t[2 * i + 1];
                    const float v0 = u0 * ta.x + u1 * ta.y + u2 * ta.z + u3 * ta.w;
                    const float v1 = u0 * tb.x + u1 * tb.y + u2 * tb.z + u3 * tb.w;
                    const unsigned h0 = __float_as_uint(v0) & 0xFFFF0000u;
                    const unsigned h1 = __float_as_uint(v1) & 0xFFFF0000u;
                    const unsigned l0 = (unsigned)__bfloat16_as_ushort(
                        __float2bfloat16(v0 - __uint_as_float(h0)));
                    const unsigned l1 = (unsigned)__bfloat16_as_ushort(
                        __float2bfloat16(v1 - __uint_as_float(h1)));
                    hw[i] = (h0 >> 16) | h1;           // (vh_c, vh_c+1)
                    lw[i] = l0 | (l1 << 16);           // (vl_c, vl_c+1)
                }
                #pragma unroll
                for (int j = 0; j < 2; j++) {
                    const unsigned u = (unsigned)(chalf * 4 + half * 2 + j);
                    const unsigned off = ((u ^ sw3) << 4);
                    asm volatile("st.shared.v4.b32 [%0], {%1,%2,%3,%4};"
                        :: "r"(Ah + off), "r"(hw[4 * j]), "r"(hw[4 * j + 1]),
                           "r"(hw[4 * j + 2]), "r"(hw[4 * j + 3]));
                    asm volatile("st.shared.v4.b32 [%0], {%1,%2,%3,%4};"
                        :: "r"(Al + off), "r"(lw[4 * j]), "r"(lw[4 * j + 1]),
                           "r"(lw[4 * j + 2]), "r"(lw[4 * j + 3]));
                }
            }

            BARRIVE(1 + s);                  // stage full
        }
    } else {
        // ================= CONSUMERS (warps 8-15) =================
        const int wc   = (tid >> 5) - 8;     // 0..7
        const int pxb  = wc & 3;
        const int oh   = wc >> 2;
        const int lane = tid & 31;
        const int pxl  = lane & 15;
        const int usel = lane >> 4;

        float acc[2][4][4];                  // [mt][ntl][quad]
        #pragma unroll
        for (int mt = 0; mt < 2; mt++)
            #pragma unroll
            for (int nt = 0; nt < 4; nt++)
                #pragma unroll
                for (int q = 0; q < 4; q++) acc[mt][nt][q] = 0.f;

        for (int k = 0; k < KK; k++) {
            const int s = k & (NSTAGE - 1);
            BSYNC(1 + s);                    // wait stage full

            const unsigned AhB = smb + (unsigned)s * A_BUF_BYTES;
            const unsigned AlB = AhB + A_PLANE;
            const uint2* wBh = g_wB + k * 2048 + lane;   // plane h
            const uint2* wBl = wBh + 1024;               // plane l

            #pragma unroll
            for (int kt = 0; kt < 4; kt++) {
                uint2 bh[4], bl[4];
                #pragma unroll
                for (int ntl = 0; ntl < 4; ntl++) {
                    const int o = kt * 256 + (oh * 4 + ntl) * 32;
                    bh[ntl] = __ldg(wBh + o);
                    bl[ntl] = __ldg(wBl + o);
                }

                unsigned ah[2][4], al[2][4];
                #pragma unroll
                for (int mt = 0; mt < 2; mt++) {
                    const int px_l = pxb * 32 + mt * 16 + pxl;
                    const unsigned u = (unsigned)(2 * kt + usel);
                    const unsigned off = (unsigned)(px_l * 128)
                                       + ((u ^ (unsigned)(px_l & 7)) << 4);
                    LDMX4(ah[mt], AhB + off);
                    LDMX4(al[mt], AlB + off);
                }

                // 3 products: Ah*Bh, Al*Bh, Ah*Bl  (ll dropped, ~2^-14)
                #pragma unroll
                for (int ntl = 0; ntl < 4; ntl++) {
                    MMA_BF16(acc[0][ntl], ah[0], bh[ntl].x, bh[ntl].y);
                    MMA_BF16(acc[1][ntl], ah[1], bh[ntl].x, bh[ntl].y);
                }
                #pragma unroll
                for (int ntl = 0; ntl < 4; ntl++) {
                    MMA_BF16(acc[0][ntl], al[0], bh[ntl].x, bh[ntl].y);
                    MMA_BF16(acc[1][ntl], al[1], bh[ntl].x, bh[ntl].y);
                }
                #pragma unroll
                for (int ntl = 0; ntl < 4; ntl++) {
                    MMA_BF16(acc[0][ntl], ah[0], bl[ntl].x, bl[ntl].y);
                    MMA_BF16(acc[1][ntl], ah[1], bl[ntl].x, bl[ntl].y);
                }
            }

            BARRIVE(5 + s);                  // stage empty
        }

        // ---------------- epilogue ----------------
        const int g = lane >> 2, tg = lane & 3;
        #pragma unroll
        for (int ntl = 0; ntl < 4; ntl++) {
            const int o = oh * 32 + ntl * 8 + 2 * tg;
            const float b0 = __ldg(bias + o);
            const float b1 = __ldg(bias + o + 1);
            float* o0 = out + (batch * O_ + o) * HW_ + ho * W_;
            float* o1 = o0 + HW_;
            #pragma unroll
            for (int mt = 0; mt < 2; mt++) {
                const int wo = pxb * 32 + mt * 16 + g;
                o0[wo]     = acc[mt][ntl][0] + b0;
                o1[wo]     = acc[mt][ntl][1] + b1;
                o0[wo + 8] = acc[mt][ntl][2] + b0;
                o1[wo + 8] = acc[mt][ntl][3] + b1;
            }
        }
    }
}

extern "C" void kernel_launch(void* const* d_in, const int* in_sizes, int n_in,
                              void* d_out, int out_size) {
    const float* x      = (const float*)d_in[0];
    const float* offset = (const float*)d_in[1];
    const float* weight = (const float*)d_in[2];
    const float* bias   = (const float*)d_in[3];
    float* out = (float*)d_out;

    cudaFuncSetAttribute(dconv_main,
                         cudaFuncAttributeMaxDynamicSharedMemorySize, SMEM_TOTAL);

    prep_all<<<NWBLK + NXBLK, 256>>>(weight, x);
    dconv_main<<<B_ * H_, 512, SMEM_TOTAL>>>(offset, bias, out);
}

// round 15
// speedup vs baseline: 1.6139x; 1.1010x over previous
#include <cuda_runtime.h>
#include <cuda_bf16.h>

#define B_   4
#define C_   64
#define O_   64
#define H_   128
#define W_   128
#define KK   9
#define HW_  (H_ * W_)

// ---------------- device scratch (allocation-free rule) ----------------
__device__ float4 g_x4[B_ * C_ * HW_];   // (x[y][x], x[y][x+1], x[y+1][x], x[y+1][x+1])
// B fragments, full-K: [k][plane(h/l)][kt(4)][nt(8)][lane(32)] uint2
__device__ uint2  g_wB[KK * 2 * 4 * 8 * 32];

#define NWBLK 144
#define NXBLK 16384

// ---------------- merged prep kernel ----------------
__global__ void prep_all(const float* __restrict__ w, const float* __restrict__ x) {
    if (blockIdx.x < NWBLK) {
        int i = blockIdx.x * 256 + threadIdx.x;      // over O*C*KK = 36864
        if (i < O_ * C_ * KK) {
            int o = i / (C_ * KK);
            int r = i - o * (C_ * KK);
            int c = r / KK;
            int k = r - c * KK;
            float v = w[i];
            unsigned hb = __float_as_uint(v) & 0xFFFF0000u;   // bf16 trunc hi
            float lf = v - __uint_as_float(hb);
            unsigned short h16 = (unsigned short)(hb >> 16);
            unsigned short l16 = __bfloat16_as_ushort(__float2bfloat16(lf));
            int kt = c >> 4, s = c & 15;
            int halfsel = s >> 3;
            int tg = (s & 7) >> 1;
            int hilo = s & 1;
            int nt = o >> 3, lane = ((o & 7) << 2) | tg;
            unsigned short* p = (unsigned short*)g_wB;
            int base = (((k * 2 + 0) * 4 + kt) * 8 * 32 + nt * 32 + lane) * 4
                     + halfsel * 2 + hilo;
            int plane_off = 4 * 8 * 32 * 4;           // 4096 ushorts
            p[base]             = h16;                // plane h
            p[base + plane_off] = l16;                // plane l
        }
    } else {
        int i = (blockIdx.x - NWBLK) * 256 + threadIdx.x;   // over B*C*HW
        int col = i & (W_ - 1);
        int y   = (i >> 7) & (H_ - 1);
        float a = x[i];
        float b = (col < W_ - 1) ? x[i + 1] : a;
        float c, d;
        if (y < H_ - 1) {
            c = x[i + W_];
            d = (col < W_ - 1) ? x[i + W_ + 1] : c;
        } else { c = a; d = b; }
        g_x4[i] = make_float4(a, b, c, d);
    }
}

// ---------------- main kernel ----------------
// 1024 blocks (batch*row*half), 256 threads, 2 CTAs/SM (256thr*128reg*2 = full RF):
//   warps 0-3 producers (64px x 2 chalf); warps 4-7 consumers (32px x 32o)
// smem: 2-stage ring, per stage 16KB: A_h [64px][64ch bf16] (8KB) then A_l (8KB)
//   row = 128B = 8 units of 16B; unit u stored at u ^ (pxl & 7)  (XOR swizzle)
#define A_BUF_BYTES 16384
#define A_PLANE     8192
#define NSTAGE      2
#define SMEM_TOTAL  (NSTAGE * A_BUF_BYTES)

// named barriers: 1+s = "stage s full", 3+s = "stage s empty"; 256 arrivals
#define BSYNC(id)   asm volatile("bar.sync %0, 256;"   :: "r"(id) : "memory")
#define BARRIVE(id) asm volatile("bar.arrive %0, 256;" :: "r"(id) : "memory")

#define LDMX4(r, addr)                                                       \
    asm volatile("ldmatrix.sync.aligned.m8n8.x4.shared.b16 {%0,%1,%2,%3}, [%4];" \
        : "=r"((r)[0]), "=r"((r)[1]), "=r"((r)[2]), "=r"((r)[3]) : "r"(addr))

#define MMA_BF16(d, a, b0, b1)                                               \
    asm volatile("mma.sync.aligned.m16n8k16.row.col.f32.bf16.bf16.f32 "      \
        "{%0,%1,%2,%3}, {%4,%5,%6,%7}, {%8,%9}, {%0,%1,%2,%3};"              \
        : "+f"((d)[0]), "+f"((d)[1]), "+f"((d)[2]), "+f"((d)[3])             \
        : "r"((a)[0]), "r"((a)[1]), "r"((a)[2]), "r"((a)[3]), "r"(b0), "r"(b1))

__global__ __launch_bounds__(256, 2)
void dconv_main(const float* __restrict__ offset,
                const float* __restrict__ bias,
                float* __restrict__ out) {
    extern __shared__ char smc[];
    unsigned smb;
    asm("{ .reg .u64 t; cvta.to.shared.u64 t, %1; cvt.u32.u64 %0, t; }"
        : "=r"(smb) : "l"(smc));

    const int tid   = threadIdx.x;
    const int half  = blockIdx.x & 1;
    const int row   = blockIdx.x >> 1;
    const int batch = row >> 7;
    const int ho    = row & 127;

    if (tid < 128) {
        // ================= PRODUCERS (warps 0-3) =================
        const int pxl   = tid & 63;          // local pixel 0..63
        const int chalf = tid >> 6;          // 32 channels each
        const int px    = half * 64 + pxl;   // pixel in row
        const float4* xb4  = g_x4 + (batch * C_ + chalf * 32) * HW_;
        const float*  offb = offset + (batch * 2 * KK) * HW_ + ho * W_ + px;

        float offy[KK], offx[KK];
        #pragma unroll
        for (int k = 0; k < KK; k++) {
            offy[k] = __ldg(offb + (2 * k) * HW_);
            offx[k] = __ldg(offb + (2 * k + 1) * HW_);
        }

        for (int k = 0; k < KK; k++) {
            const int s = k & (NSTAGE - 1);
            if (k >= NSTAGE) BSYNC(3 + s);   // wait stage empty

            // bilinear corner math (proven)
            const int ki = k / 3, kj = k - ki * 3;
            const float py  = offy[k] + (float)(ki - 1 + ho);
            const float pxx = offx[k] + (float)(kj - 1 + px);
            const float y0f = floorf(py), x0f = floorf(pxx);
            const float ly = py - y0f,  lx = pxx - x0f;
            const float hy = 1.f - ly,  hx = 1.f - lx;
            const int y0 = (int)y0f, x0 = (int)x0f;

            int ybase; float w_top, w_bot;
            if (y0 >= 0) {
                ybase = min(y0, H_ - 1);
                w_top = (y0 < H_)     ? hy : 0.f;
                w_bot = (y0 < H_ - 1) ? ly : 0.f;
            } else {
                ybase = 0;
                w_top = (y0 == -1) ? ly : 0.f;
                w_bot = 0.f;
            }
            float wa, wb;
            if (x0 >= 0 && x0 < W_) { wa = hx; wb = (x0 < W_ - 1) ? lx : 0.f; }
            else if (x0 == -1)      { wa = lx; wb = 0.f; }
            else                    { wa = 0.f; wb = 0.f; }
            const int bx = min(max(x0, 0), W_ - 1);

            const float u0 = w_top * wa, u1 = w_top * wb;
            const float u2 = w_bot * wa, u3 = w_bot * wb;

            const float4* q = xb4 + ybase * W_ + bx;
            const unsigned Ah = smb + (unsigned)s * A_BUF_BYTES + (unsigned)(pxl * 128);
            const unsigned Al = Ah + A_PLANE;
            const unsigned sw3 = (unsigned)(pxl & 7);

            // 2 batches of 16 front-issued gathers (MLP=16)
            #pragma unroll
            for (int hb2 = 0; hb2 < 2; hb2++) {
                float4 t[16];
                #pragma unroll
                for (int cc = 0; cc < 16; cc++)
                    t[cc] = __ldg(q + (hb2 * 16 + cc) * HW_);

                unsigned hw[8], lw[8];
                #pragma unroll
                for (int i = 0; i < 8; i++) {
                    const float4 ta = t[2 * i], tb = t[2 * i + 1];
                    const float v0 = u0 * ta.x + u1 * ta.y + u2 * ta.z + u3 * ta.w;
                    const float v1 = u0 * tb.x + u1 * tb.y + u2 * tb.z + u3 * tb.w;
                    const unsigned h0 = __float_as_uint(v0) & 0xFFFF0000u;
                    const unsigned h1 = __float_as_uint(v1) & 0xFFFF0000u;
                    const unsigned l0 = (unsigned)__bfloat16_as_ushort(
                        __float2bfloat16(v0 - __uint_as_float(h0)));
                    const unsigned l1 = (unsigned)__bfloat16_as_ushort(
                        __float2bfloat16(v1 - __uint_as_float(h1)));
                    hw[i] = (h0 >> 16) | h1;           // (vh_c, vh_c+1)
                    lw[i] = l0 | (l1 << 16);           // (vl_c, vl_c+1)
                }
                #pragma unroll
                for (int j = 0; j < 2; j++) {
                    const unsigned u = (unsigned)(chalf * 4 + hb2 * 2 + j);
                    const unsigned off = ((u ^ sw3) << 4);
                    asm volatile("st.shared.v4.b32 [%0], {%1,%2,%3,%4};"
                        :: "r"(Ah + off), "r"(hw[4 * j]), "r"(hw[4 * j + 1]),
                           "r"(hw[4 * j + 2]), "r"(hw[4 * j + 3]));
                    asm volatile("st.shared.v4.b32 [%0], {%1,%2,%3,%4};"
                        :: "r"(Al + off), "r"(lw[4 * j]), "r"(lw[4 * j + 1]),
                           "r"(lw[4 * j + 2]), "r"(lw[4 * j + 3]));
                }
            }

            BARRIVE(1 + s);                  // stage full
        }
    } else {
        // ================= CONSUMERS (warps 4-7) =================
        const int wc   = (tid >> 5) - 4;     // 0..3
        const int pxb  = wc & 1;             // 32-px block within 64
        const int oh   = wc >> 1;            // 32-o half
        const int lane = tid & 31;
        const int pxll = lane & 15;
        const int usel = lane >> 4;

        float acc[2][4][4];                  // [mt][ntl][quad]
        #pragma unroll
        for (int mt = 0; mt < 2; mt++)
            #pragma unroll
            for (int nt = 0; nt < 4; nt++)
                #pragma unroll
                for (int q = 0; q < 4; q++) acc[mt][nt][q] = 0.f;

        for (int k = 0; k < KK; k++) {
            const int s = k & (NSTAGE - 1);
            BSYNC(1 + s);                    // wait stage full

            const unsigned AhB = smb + (unsigned)s * A_BUF_BYTES;
            const unsigned AlB = AhB + A_PLANE;
            const uint2* wBh = g_wB + k * 2048 + lane;   // plane h
            const uint2* wBl = wBh + 1024;               // plane l

            #pragma unroll
            for (int kt = 0; kt < 4; kt++) {
                uint2 bh[4], bl[4];
                #pragma unroll
                for (int ntl = 0; ntl < 4; ntl++) {
                    const int o = kt * 256 + (oh * 4 + ntl) * 32;
                    bh[ntl] = __ldg(wBh + o);
                    bl[ntl] = __ldg(wBl + o);
                }

                unsigned ah[2][4], al[2][4];
                #pragma unroll
                for (int mt = 0; mt < 2; mt++) {
                    const int px_l = pxb * 32 + mt * 16 + pxll;   // 0..63
                    const unsigned u = (unsigned)(2 * kt + usel);
                    const unsigned off = (unsigned)(px_l * 128)
                                       + ((u ^ (unsigned)(px_l & 7)) << 4);
                    LDMX4(ah[mt], AhB + off);
                    LDMX4(al[mt], AlB + off);
                }

                // 3 products: Ah*Bh, Al*Bh, Ah*Bl  (ll dropped, ~2^-14)
                #pragma unroll
                for (int ntl = 0; ntl < 4; ntl++) {
                    MMA_BF16(acc[0][ntl], ah[0], bh[ntl].x, bh[ntl].y);
                    MMA_BF16(acc[1][ntl], ah[1], bh[ntl].x, bh[ntl].y);
                }
                #pragma unroll
                for (int ntl = 0; ntl < 4; ntl++) {
                    MMA_BF16(acc[0][ntl], al[0], bh[ntl].x, bh[ntl].y);
                    MMA_BF16(acc[1][ntl], al[1], bh[ntl].x, bh[ntl].y);
                }
                #pragma unroll
                for (int ntl = 0; ntl < 4; ntl++) {
                    MMA_BF16(acc[0][ntl], ah[0], bl[ntl].x, bl[ntl].y);
                    MMA_BF16(acc[1][ntl], ah[1], bl[ntl].x, bl[ntl].y);
                }
            }

            BARRIVE(3 + s);                  // stage empty
        }

        // ---------------- epilogue ----------------
        const int g = lane >> 2, tg = lane & 3;
        #pragma unroll
        for (int ntl = 0; ntl < 4; ntl++) {
            const int o = oh * 32 + ntl * 8 + 2 * tg;
            const float b0 = __ldg(bias + o);
            const float b1 = __ldg(bias + o + 1);
            float* o0 = out + (batch * O_ + o) * HW_ + ho * W_ + half * 64;
            float* o1 = o0 + HW_;
            #pragma unroll
            for (int mt = 0; mt < 2; mt++) {
                const int wo = pxb * 32 + mt * 16 + g;
                o0[wo]     = acc[mt][ntl][0] + b0;
                o1[wo]     = acc[mt][ntl][1] + b1;
                o0[wo + 8] = acc[mt][ntl][2] + b0;
                o1[wo + 8] = acc[mt][ntl][3] + b1;
            }
        }
    }
}

extern "C" void kernel_launch(void* const* d_in, const int* in_sizes, int n_in,
                              void* d_out, int out_size) {
    const float* x      = (const float*)d_in[0];
    const float* offset = (const float*)d_in[1];
    const float* weight = (const float*)d_in[2];
    const float* bias   = (const float*)d_in[3];
    float* out = (float*)d_out;

    cudaFuncSetAttribute(dconv_main,
                         cudaFuncAttributeMaxDynamicSharedMemorySize, SMEM_TOTAL);

    prep_all<<<NWBLK + NXBLK, 256>>>(weight, x);
    dconv_main<<<2 * B_ * H_, 256, SMEM_TOTAL>>>(offset, bias, out);
}

// round 16
// speedup vs baseline: 2.1618x; 1.3395x over previous
#include <cuda_runtime.h>
#include <cuda_bf16.h>
#include <cuda_fp16.h>

#define B_   4
#define C_   64
#define O_   64
#define H_   128
#define W_   128
#define KK   9
#define HW_  (H_ * W_)

// ---------------- device scratch (allocation-free rule) ----------------
// fp16 corner pack: (x[y][x], x[y][x+1], x[y+1][x], x[y+1][x+1]) as half4 in uint2
__device__ uint2 g_x4h[B_ * C_ * HW_];
// B fragments, full-K: [k][plane(h/l)][kt(4)][nt(8)][lane(32)] uint2
__device__ uint2 g_wB[KK * 2 * 4 * 8 * 32];

#define NWBLK 144
#define NXBLK 16384

// ---------------- merged prep kernel ----------------
__global__ void prep_all(const float* __restrict__ w, const float* __restrict__ x) {
    if (blockIdx.x < NWBLK) {
        int i = blockIdx.x * 256 + threadIdx.x;      // over O*C*KK = 36864
        if (i < O_ * C_ * KK) {
            int o = i / (C_ * KK);
            int r = i - o * (C_ * KK);
            int c = r / KK;
            int k = r - c * KK;
            float v = w[i];
            unsigned hb = __float_as_uint(v) & 0xFFFF0000u;   // bf16 trunc hi
            float lf = v - __uint_as_float(hb);
            unsigned short h16 = (unsigned short)(hb >> 16);
            unsigned short l16 = __bfloat16_as_ushort(__float2bfloat16(lf));
            int kt = c >> 4, s = c & 15;
            int halfsel = s >> 3;
            int tg = (s & 7) >> 1;
            int hilo = s & 1;
            int nt = o >> 3, lane = ((o & 7) << 2) | tg;
            unsigned short* p = (unsigned short*)g_wB;
            int base = (((k * 2 + 0) * 4 + kt) * 8 * 32 + nt * 32 + lane) * 4
                     + halfsel * 2 + hilo;
            int plane_off = 4 * 8 * 32 * 4;           // 4096 ushorts
            p[base]             = h16;                // plane h
            p[base + plane_off] = l16;                // plane l
        }
    } else {
        int i = (blockIdx.x - NWBLK) * 256 + threadIdx.x;   // over B*C*HW
        int col = i & (W_ - 1);
        int y   = (i >> 7) & (H_ - 1);
        float a = x[i];
        float b = (col < W_ - 1) ? x[i + 1] : a;
        float c, d;
        if (y < H_ - 1) {
            c = x[i + W_];
            d = (col < W_ - 1) ? x[i + W_ + 1] : c;
        } else { c = a; d = b; }
        __half2 ab = __floats2half2_rn(a, b);
        __half2 cd = __floats2half2_rn(c, d);
        uint2 v2;
        v2.x = *(unsigned*)&ab;
        v2.y = *(unsigned*)&cd;
        g_x4h[i] = v2;
    }
}

// ---------------- main kernel ----------------
// 1024 blocks (batch*row*half), 256 threads, 2 CTAs/SM:
//   warps 0-3 producers (64px x 2 chalf); warps 4-7 consumers (32px x 32o)
// smem: 2-stage ring, per stage 16KB: A_h [64px][64ch bf16] (8KB) then A_l (8KB)
//   row = 128B = 8 units of 16B; unit u stored at u ^ (pxl & 7)  (XOR swizzle)
#define A_BUF_BYTES 16384
#define A_PLANE     8192
#define NSTAGE      2
#define SMEM_TOTAL  (NSTAGE * A_BUF_BYTES)

// named barriers: 1+s = "stage s full", 3+s = "stage s empty"; 256 arrivals
#define BSYNC(id)   asm volatile("bar.sync %0, 256;"   :: "r"(id) : "memory")
#define BARRIVE(id) asm volatile("bar.arrive %0, 256;" :: "r"(id) : "memory")

#define LDMX4(r, addr)                                                       \
    asm volatile("ldmatrix.sync.aligned.m8n8.x4.shared.b16 {%0,%1,%2,%3}, [%4];" \
        : "=r"((r)[0]), "=r"((r)[1]), "=r"((r)[2]), "=r"((r)[3]) : "r"(addr))

#define MMA_BF16(d, a, b0, b1)                                               \
    asm volatile("mma.sync.aligned.m16n8k16.row.col.f32.bf16.bf16.f32 "      \
        "{%0,%1,%2,%3}, {%4,%5,%6,%7}, {%8,%9}, {%0,%1,%2,%3};"              \
        : "+f"((d)[0]), "+f"((d)[1]), "+f"((d)[2]), "+f"((d)[3])             \
        : "r"((a)[0]), "r"((a)[1]), "r"((a)[2]), "r"((a)[3]), "r"(b0), "r"(b1))

__global__ __launch_bounds__(256, 2)
void dconv_main(const float* __restrict__ offset,
                const float* __restrict__ bias,
                float* __restrict__ out) {
    extern __shared__ char smc[];
    unsigned smb;
    asm("{ .reg .u64 t; cvta.to.shared.u64 t, %1; cvt.u32.u64 %0, t; }"
        : "=r"(smb) : "l"(smc));

    const int tid   = threadIdx.x;
    const int half  = blockIdx.x & 1;
    const int row   = blockIdx.x >> 1;
    const int batch = row >> 7;
    const int ho    = row & 127;

    if (tid < 128) {
        // ================= PRODUCERS (warps 0-3) =================
        const int pxl   = tid & 63;          // local pixel 0..63
        const int chalf = tid >> 6;          // 32 channels each
        const int px    = half * 64 + pxl;   // pixel in row
        const uint2* xb4  = g_x4h + (batch * C_ + chalf * 32) * HW_;
        const float* offb = offset + (batch * 2 * KK) * HW_ + ho * W_ + px;

        float offy[KK], offx[KK];
        #pragma unroll
        for (int k = 0; k < KK; k++) {
            offy[k] = __ldg(offb + (2 * k) * HW_);
            offx[k] = __ldg(offb + (2 * k + 1) * HW_);
        }

        for (int k = 0; k < KK; k++) {
            const int s = k & (NSTAGE - 1);
            if (k >= NSTAGE) BSYNC(3 + s);   // wait stage empty

            // bilinear corner math (proven)
            const int ki = k / 3, kj = k - ki * 3;
            const float py  = offy[k] + (float)(ki - 1 + ho);
            const float pxx = offx[k] + (float)(kj - 1 + px);
            const float y0f = floorf(py), x0f = floorf(pxx);
            const float ly = py - y0f,  lx = pxx - x0f;
            const float hy = 1.f - ly,  hx = 1.f - lx;
            const int y0 = (int)y0f, x0 = (int)x0f;

            int ybase; float w_top, w_bot;
            if (y0 >= 0) {
                ybase = min(y0, H_ - 1);
                w_top = (y0 < H_)     ? hy : 0.f;
                w_bot = (y0 < H_ - 1) ? ly : 0.f;
            } else {
                ybase = 0;
                w_top = (y0 == -1) ? ly : 0.f;
                w_bot = 0.f;
            }
            float wa, wb;
            if (x0 >= 0 && x0 < W_) { wa = hx; wb = (x0 < W_ - 1) ? lx : 0.f; }
            else if (x0 == -1)      { wa = lx; wb = 0.f; }
            else                    { wa = 0.f; wb = 0.f; }
            const int bx = min(max(x0, 0), W_ - 1);

            const float u0 = w_top * wa, u1 = w_top * wb;
            const float u2 = w_bot * wa, u3 = w_bot * wb;

            const uint2* q = xb4 + ybase * W_ + bx;
            const unsigned Ah = smb + (unsigned)s * A_BUF_BYTES + (unsigned)(pxl * 128);
            const unsigned Al = Ah + A_PLANE;
            const unsigned sw3 = (unsigned)(pxl & 7);

            // 2 batches of 16 front-issued LDG.64 gathers (MLP=16)
            #pragma unroll
            for (int hb2 = 0; hb2 < 2; hb2++) {
                uint2 t[16];
                #pragma unroll
                for (int cc = 0; cc < 16; cc++)
                    t[cc] = __ldg(q + (hb2 * 16 + cc) * HW_);

                unsigned hw[8], lw[8];
                #pragma unroll
                for (int i = 0; i < 8; i++) {
                    const uint2 ra = t[2 * i], rb = t[2 * i + 1];
                    const float2 a01 = __half22float2(*(const __half2*)&ra.x);
                    const float2 a23 = __half22float2(*(const __half2*)&ra.y);
                    const float2 b01 = __half22float2(*(const __half2*)&rb.x);
                    const float2 b23 = __half22float2(*(const __half2*)&rb.y);
                    const float v0 = u0 * a01.x + u1 * a01.y + u2 * a23.x + u3 * a23.y;
                    const float v1 = u0 * b01.x + u1 * b01.y + u2 * b23.x + u3 * b23.y;
                    const unsigned h0 = __float_as_uint(v0) & 0xFFFF0000u;
                    const unsigned h1 = __float_as_uint(v1) & 0xFFFF0000u;
                    const unsigned l0 = (unsigned)__bfloat16_as_ushort(
                        __float2bfloat16(v0 - __uint_as_float(h0)));
                    const unsigned l1 = (unsigned)__bfloat16_as_ushort(
                        __float2bfloat16(v1 - __uint_as_float(h1)));
                    hw[i] = (h0 >> 16) | h1;           // (vh_c, vh_c+1)
                    lw[i] = l0 | (l1 << 16);           // (vl_c, vl_c+1)
                }
                #pragma unroll
                for (int j = 0; j < 2; j++) {
                    const unsigned u = (unsigned)(chalf * 4 + hb2 * 2 + j);
                    const unsigned off = ((u ^ sw3) << 4);
                    asm volatile("st.shared.v4.b32 [%0], {%1,%2,%3,%4};"
                        :: "r"(Ah + off), "r"(hw[4 * j]), "r"(hw[4 * j + 1]),
                           "r"(hw[4 * j + 2]), "r"(hw[4 * j + 3]));
                    asm volatile("st.shared.v4.b32 [%0], {%1,%2,%3,%4};"
                        :: "r"(Al + off), "r"(lw[4 * j]), "r"(lw[4 * j + 1]),
                           "r"(lw[4 * j + 2]), "r"(lw[4 * j + 3]));
                }
            }

            BARRIVE(1 + s);                  // stage full
        }
    } else {
        // ================= CONSUMERS (warps 4-7) =================
        const int wc   = (tid >> 5) - 4;     // 0..3
        const int pxb  = wc & 1;             // 32-px block within 64
        const int oh   = wc >> 1;            // 32-o half
        const int lane = tid & 31;
        const int pxll = lane & 15;
        const int usel = lane >> 4;

        float acc[2][4][4];                  // [mt][ntl][quad]
        #pragma unroll
        for (int mt = 0; mt < 2; mt++)
            #pragma unroll
            for (int nt = 0; nt < 4; nt++)
                #pragma unroll
                for (int q = 0; q < 4; q++) acc[mt][nt][q] = 0.f;

        for (int k = 0; k < KK; k++) {
            const int s = k & (NSTAGE - 1);
            BSYNC(1 + s);                    // wait stage full

            const unsigned AhB = smb + (unsigned)s * A_BUF_BYTES;
            const unsigned AlB = AhB + A_PLANE;
            const uint2* wBh = g_wB + k * 2048 + lane;   // plane h
            const uint2* wBl = wBh + 1024;               // plane l

            #pragma unroll
            for (int kt = 0; kt < 4; kt++) {
                uint2 bh[4], bl[4];
                #pragma unroll
                for (int ntl = 0; ntl < 4; ntl++) {
                    const int o = kt * 256 + (oh * 4 + ntl) * 32;
                    bh[ntl] = __ldg(wBh + o);
                    bl[ntl] = __ldg(wBl + o);
                }

                unsigned ah[2][4], al[2][4];
                #pragma unroll
                for (int mt = 0; mt < 2; mt++) {
                    const int px_l = pxb * 32 + mt * 16 + pxll;   // 0..63
                    const unsigned u = (unsigned)(2 * kt + usel);
                    const unsigned off = (unsigned)(px_l * 128)
                                       + ((u ^ (unsigned)(px_l & 7)) << 4);
                    LDMX4(ah[mt], AhB + off);
                    LDMX4(al[mt], AlB + off);
                }

                // 3 products: Ah*Bh, Al*Bh, Ah*Bl  (ll dropped, ~2^-14)
                #pragma unroll
                for (int ntl = 0; ntl < 4; ntl++) {
                    MMA_BF16(acc[0][ntl], ah[0], bh[ntl].x, bh[ntl].y);
                    MMA_BF16(acc[1][ntl], ah[1], bh[ntl].x, bh[ntl].y);
                }
                #pragma unroll
                for (int ntl = 0; ntl < 4; ntl++) {
                    MMA_BF16(acc[0][ntl], al[0], bh[ntl].x, bh[ntl].y);
                    MMA_BF16(acc[1][ntl], al[1], bh[ntl].x, bh[ntl].y);
                }
                #pragma unroll
                for (int ntl = 0; ntl < 4; ntl++) {
                    MMA_BF16(acc[0][ntl], ah[0], bl[ntl].x, bl[ntl].y);
                    MMA_BF16(acc[1][ntl], ah[1], bl[ntl].x, bl[ntl].y);
                }
            }

            BARRIVE(3 + s);                  // stage empty
        }

        // ---------------- epilogue ----------------
        const int g = lane >> 2, tg = lane & 3;
        #pragma unroll
        for (int ntl = 0; ntl < 4; ntl++) {
            const int o = oh * 32 + ntl * 8 + 2 * tg;
            const float b0 = __ldg(bias + o);
            const float b1 = __ldg(bias + o + 1);
            float* o0 = out + (batch * O_ + o) * HW_ + ho * W_ + half * 64;
            float* o1 = o0 + HW_;
            #pragma unroll
            for (int mt = 0; mt < 2; mt++) {
                const int wo = pxb * 32 + mt * 16 + g;
                o0[wo]     = acc[mt][ntl][0] + b0;
                o1[wo]     = acc[mt][ntl][1] + b1;
                o0[wo + 8] = acc[mt][ntl][2] + b0;
                o1[wo + 8] = acc[mt][ntl][3] + b1;
            }
        }
    }
}

extern "C" void kernel_launch(void* const* d_in, const int* in_sizes, int n_in,
                              void* d_out, int out_size) {
    const float* x      = (const float*)d_in[0];
    const float* offset = (const float*)d_in[1];
    const float* weight = (const float*)d_in[2];
    const float* bias   = (const float*)d_in[3];
    float* out = (float*)d_out;

    cudaFuncSetAttribute(dconv_main,
                         cudaFuncAttributeMaxDynamicSharedMemorySize, SMEM_TOTAL);

    prep_all<<<NWBLK + NXBLK, 256>>>(weight, x);
    dconv_main<<<2 * B_ * H_, 256, SMEM_TOTAL>>>(offset, bias, out);
}

// round 17
// speedup vs baseline: 2.3758x; 1.0990x over previous
#include <cuda_runtime.h>
#include <cuda_fp16.h>

#define B_   4
#define C_   64
#define O_   64
#define H_   128
#define W_   128
#define KK   9
#define HW_  (H_ * W_)

// ---------------- device scratch (allocation-free rule) ----------------
// fp16 corner pack: (x[y][x], x[y][x+1], x[y+1][x], x[y+1][x+1]) as half4 in uint2
__device__ uint2 g_x4h[B_ * C_ * HW_];
// B fragments, single fp16 plane: [k][kt(4)][nt(8)][lane(32)] uint2
__device__ uint2 g_wB[KK * 4 * 8 * 32];

#define NWBLK 144
#define NXBLK 16384

// ---------------- merged prep kernel ----------------
__global__ void prep_all(const float* __restrict__ w, const float* __restrict__ x) {
    if (blockIdx.x < NWBLK) {
        int i = blockIdx.x * 256 + threadIdx.x;      // over O*C*KK = 36864
        if (i < O_ * C_ * KK) {
            int o = i / (C_ * KK);
            int r = i - o * (C_ * KK);
            int c = r / KK;
            int k = r - c * KK;
            __half hv = __float2half(w[i]);
            unsigned short h16 = __half_as_ushort(hv);
            int kt = c >> 4, s = c & 15;
            int halfsel = s >> 3;          // b0 vs b1 (k vs k+8)
            int tg = (s & 7) >> 1;
            int hilo = s & 1;
            int nt = o >> 3, lane = ((o & 7) << 2) | tg;
            unsigned short* p = (unsigned short*)g_wB;
            int base = ((k * 4 + kt) * 8 * 32 + nt * 32 + lane) * 4
                     + halfsel * 2 + hilo;
            p[base] = h16;
        }
    } else {
        int i = (blockIdx.x - NWBLK) * 256 + threadIdx.x;   // over B*C*HW
        int col = i & (W_ - 1);
        int y   = (i >> 7) & (H_ - 1);
        float a = x[i];
        float b = (col < W_ - 1) ? x[i + 1] : a;
        float c, d;
        if (y < H_ - 1) {
            c = x[i + W_];
            d = (col < W_ - 1) ? x[i + W_ + 1] : c;
        } else { c = a; d = b; }
        __half2 ab = __floats2half2_rn(a, b);
        __half2 cd = __floats2half2_rn(c, d);
        uint2 v2;
        v2.x = *(unsigned*)&ab;
        v2.y = *(unsigned*)&cd;
        g_x4h[i] = v2;
    }
}

// ---------------- main kernel ----------------
// 1024 blocks (batch*row*half), 256 threads, 2 CTAs/SM:
//   warps 0-3 producers (64px x 2 chalf); warps 4-7 consumers (32px x 32o)
// smem: 2-stage ring, per stage 8KB: A [64px][64ch fp16]
//   row = 128B = 8 units of 16B; unit u stored at u ^ (pxl & 7)  (XOR swizzle)
#define A_BUF_BYTES 8192
#define NSTAGE      2
#define SMEM_TOTAL  (NSTAGE * A_BUF_BYTES)

// named barriers: 1+s = "stage s full", 3+s = "stage s empty"; 256 arrivals
#define BSYNC(id)   asm volatile("bar.sync %0, 256;"   :: "r"(id) : "memory")
#define BARRIVE(id) asm volatile("bar.arrive %0, 256;" :: "r"(id) : "memory")

#define LDMX4(r, addr)                                                       \
    asm volatile("ldmatrix.sync.aligned.m8n8.x4.shared.b16 {%0,%1,%2,%3}, [%4];" \
        : "=r"((r)[0]), "=r"((r)[1]), "=r"((r)[2]), "=r"((r)[3]) : "r"(addr))

#define MMA_F16(d, a, b0, b1)                                                \
    asm volatile("mma.sync.aligned.m16n8k16.row.col.f32.f16.f16.f32 "        \
        "{%0,%1,%2,%3}, {%4,%5,%6,%7}, {%8,%9}, {%0,%1,%2,%3};"              \
        : "+f"((d)[0]), "+f"((d)[1]), "+f"((d)[2]), "+f"((d)[3])             \
        : "r"((a)[0]), "r"((a)[1]), "r"((a)[2]), "r"((a)[3]), "r"(b0), "r"(b1))

__global__ __launch_bounds__(256, 2)
void dconv_main(const float* __restrict__ offset,
                const float* __restrict__ bias,
                float* __restrict__ out) {
    extern __shared__ char smc[];
    unsigned smb;
    asm("{ .reg .u64 t; cvta.to.shared.u64 t, %1; cvt.u32.u64 %0, t; }"
        : "=r"(smb) : "l"(smc));

    const int tid   = threadIdx.x;
    const int half  = blockIdx.x & 1;
    const int row   = blockIdx.x >> 1;
    const int batch = row >> 7;
    const int ho    = row & 127;

    if (tid < 128) {
        // ================= PRODUCERS (warps 0-3) =================
        const int pxl   = tid & 63;          // local pixel 0..63
        const int chalf = tid >> 6;          // 32 channels each
        const int px    = half * 64 + pxl;   // pixel in row
        const uint2* xb4  = g_x4h + (batch * C_ + chalf * 32) * HW_;
        const float* offb = offset + (batch * 2 * KK) * HW_ + ho * W_ + px;

        float offy[KK], offx[KK];
        #pragma unroll
        for (int k = 0; k < KK; k++) {
            offy[k] = __ldg(offb + (2 * k) * HW_);
            offx[k] = __ldg(offb + (2 * k + 1) * HW_);
        }

        for (int k = 0; k < KK; k++) {
            const int s = k & (NSTAGE - 1);
            if (k >= NSTAGE) BSYNC(3 + s);   // wait stage empty

            // bilinear corner math (proven)
            const int ki = k / 3, kj = k - ki * 3;
            const float py  = offy[k] + (float)(ki - 1 + ho);
            const float pxx = offx[k] + (float)(kj - 1 + px);
            const float y0f = floorf(py), x0f = floorf(pxx);
            const float ly = py - y0f,  lx = pxx - x0f;
            const float hy = 1.f - ly,  hx = 1.f - lx;
            const int y0 = (int)y0f, x0 = (int)x0f;

            int ybase; float w_top, w_bot;
            if (y0 >= 0) {
                ybase = min(y0, H_ - 1);
                w_top = (y0 < H_)     ? hy : 0.f;
                w_bot = (y0 < H_ - 1) ? ly : 0.f;
            } else {
                ybase = 0;
                w_top = (y0 == -1) ? ly : 0.f;
                w_bot = 0.f;
            }
            float wa, wb;
            if (x0 >= 0 && x0 < W_) { wa = hx; wb = (x0 < W_ - 1) ? lx : 0.f; }
            else if (x0 == -1)      { wa = lx; wb = 0.f; }
            else                    { wa = 0.f; wb = 0.f; }
            const int bx = min(max(x0, 0), W_ - 1);

            const float u0 = w_top * wa, u1 = w_top * wb;
            const float u2 = w_bot * wa, u3 = w_bot * wb;

            const uint2* q = xb4 + ybase * W_ + bx;
            const unsigned Arow = smb + (unsigned)s * A_BUF_BYTES
                                + (unsigned)(pxl * 128);
            const unsigned sw3 = (unsigned)(pxl & 7);

            // 2 batches of 16 front-issued LDG.64 gathers (MLP=16)
            #pragma unroll
            for (int hb2 = 0; hb2 < 2; hb2++) {
                uint2 t[16];
                #pragma unroll
                for (int cc = 0; cc < 16; cc++)
                    t[cc] = __ldg(q + (hb2 * 16 + cc) * HW_);

                unsigned hw[8];
                #pragma unroll
                for (int i = 0; i < 8; i++) {
                    const uint2 ra = t[2 * i], rb = t[2 * i + 1];
                    const float2 a01 = __half22float2(*(const __half2*)&ra.x);
                    const float2 a23 = __half22float2(*(const __half2*)&ra.y);
                    const float2 b01 = __half22float2(*(const __half2*)&rb.x);
                    const float2 b23 = __half22float2(*(const __half2*)&rb.y);
                    const float v0 = u0 * a01.x + u1 * a01.y + u2 * a23.x + u3 * a23.y;
                    const float v1 = u0 * b01.x + u1 * b01.y + u2 * b23.x + u3 * b23.y;
                    const __half2 p01 = __floats2half2_rn(v0, v1);
                    hw[i] = *(const unsigned*)&p01;    // (v_c, v_c+1) fp16
                }
                #pragma unroll
                for (int j = 0; j < 2; j++) {
                    const unsigned u = (unsigned)(chalf * 4 + hb2 * 2 + j);
                    const unsigned off = ((u ^ sw3) << 4);
                    asm volatile("st.shared.v4.b32 [%0], {%1,%2,%3,%4};"
                        :: "r"(Arow + off), "r"(hw[4 * j]), "r"(hw[4 * j + 1]),
                           "r"(hw[4 * j + 2]), "r"(hw[4 * j + 3]));
                }
            }

            BARRIVE(1 + s);                  // stage full
        }
    } else {
        // ================= CONSUMERS (warps 4-7) =================
        const int wc   = (tid >> 5) - 4;     // 0..3
        const int pxb  = wc & 1;             // 32-px block within 64
        const int oh   = wc >> 1;            // 32-o half
        const int lane = tid & 31;
        const int pxll = lane & 15;
        const int usel = lane >> 4;

        float acc[2][4][4];                  // [mt][ntl][quad]
        #pragma unroll
        for (int mt = 0; mt < 2; mt++)
            #pragma unroll
            for (int nt = 0; nt < 4; nt++)
                #pragma unroll
                for (int q = 0; q < 4; q++) acc[mt][nt][q] = 0.f;

        for (int k = 0; k < KK; k++) {
            const int s = k & (NSTAGE - 1);
            BSYNC(1 + s);                    // wait stage full

            const unsigned AB = smb + (unsigned)s * A_BUF_BYTES;
            const uint2* wB = g_wB + k * 1024 + lane;

            #pragma unroll
            for (int kt = 0; kt < 4; kt++) {
                uint2 bq[4];
                #pragma unroll
                for (int ntl = 0; ntl < 4; ntl++)
                    bq[ntl] = __ldg(wB + kt * 256 + (oh * 4 + ntl) * 32);

                unsigned a[2][4];
                #pragma unroll
                for (int mt = 0; mt < 2; mt++) {
                    const int px_l = pxb * 32 + mt * 16 + pxll;   // 0..63
                    const unsigned u = (unsigned)(2 * kt + usel);
                    const unsigned off = (unsigned)(px_l * 128)
                                       + ((u ^ (unsigned)(px_l & 7)) << 4);
                    LDMX4(a[mt], AB + off);
                }

                #pragma unroll
                for (int ntl = 0; ntl < 4; ntl++) {
                    MMA_F16(acc[0][ntl], a[0], bq[ntl].x, bq[ntl].y);
                    MMA_F16(acc[1][ntl], a[1], bq[ntl].x, bq[ntl].y);
                }
            }

            BARRIVE(3 + s);                  // stage empty
        }

        // ---------------- epilogue ----------------
        const int g = lane >> 2, tg = lane & 3;
        #pragma unroll
        for (int ntl = 0; ntl < 4; ntl++) {
            const int o = oh * 32 + ntl * 8 + 2 * tg;
            const float b0 = __ldg(bias + o);
            const float b1 = __ldg(bias + o + 1);
            float* o0 = out + (batch * O_ + o) * HW_ + ho * W_ + half * 64;
            float* o1 = o0 + HW_;
            #pragma unroll
            for (int mt = 0; mt < 2; mt++) {
                const int wo = pxb * 32 + mt * 16 + g;
                o0[wo]     = acc[mt][ntl][0] + b0;
                o1[wo]     = acc[mt][ntl][1] + b1;
                o0[wo + 8] = acc[mt][ntl][2] + b0;
                o1[wo + 8] = acc[mt][ntl][3] + b1;
            }
        }
    }
}

extern "C" void kernel_launch(void* const* d_in, const int* in_sizes, int n_in,
                              void* d_out, int out_size) {
    const float* x      = (const float*)d_in[0];
    const float* offset = (const float*)d_in[1];
    const float* weight = (const float*)d_in[2];
    const float* bias   = (const float*)d_in[3];
    float* out = (float*)d_out;

    cudaFuncSetAttribute(dconv_main,
                         cudaFuncAttributeMaxDynamicSharedMemorySize, SMEM_TOTAL);

    prep_all<<<NWBLK + NXBLK, 256>>>(weight, x);
    dconv_main<<<2 * B_ * H_, 256, SMEM_TOTAL>>>(offset, bias, out);
}